// round 1
// baseline (speedup 1.0000x reference)
#include <cuda_runtime.h>
#include <cstdint>

#define NSTEPS 64
#define DD 16
#define ROWS_PER_CTA 512
// W: 64*16*16 floats (64KB) + V: 64KB  => 128KB dynamic smem
#define WEIGHT_FLOATS (NSTEPS * DD * DD)
#define SMEM_BYTES (2 * WEIGHT_FLOATS * 4)

typedef unsigned long long u64;

// ---- packed f32x2 helpers (sm_103a) ----
__device__ __forceinline__ u64 pack2(float lo, float hi) {
    u64 r;
    asm("mov.b64 %0, {%1, %2};" : "=l"(r) : "f"(lo), "f"(hi));
    return r;
}
__device__ __forceinline__ void unpack2(u64 v, float& lo, float& hi) {
    asm("mov.b64 {%0, %1}, %2;" : "=f"(lo), "=f"(hi) : "l"(v));
}
__device__ __forceinline__ u64 fma2(u64 a, u64 b, u64 c) {
    u64 d;
    asm("fma.rn.f32x2 %0, %1, %2, %3;" : "=l"(d) : "l"(a), "l"(b), "l"(c));
    return d;
}

__device__ __forceinline__ float gelu_exact(float x) {
    // exact (erf) GELU, matching torch.nn.GELU default / jax approximate=False
    return 0.5f * x * (1.0f + erff(x * 0.70710678118654752440f));
}

__global__ __launch_bounds__(ROWS_PER_CTA)
void resnet_steps_kernel(const float* __restrict__ x,
                         const float* __restrict__ W,
                         const float* __restrict__ V,
                         float* __restrict__ out)
{
    extern __shared__ float smem[];        // [0, 16384): W ; [16384, 32768): V * (1/64)
    const int tid = threadIdx.x;

    // Cooperative weight load. V is pre-scaled by 1/NSTEPS so the residual
    // add folds into the second matvec accumulation.
    {
        const float4* Wg = reinterpret_cast<const float4*>(W);
        const float4* Vg = reinterpret_cast<const float4*>(V);
        float4* sW4 = reinterpret_cast<float4*>(smem);
        float4* sV4 = reinterpret_cast<float4*>(smem + WEIGHT_FLOATS);
        const float invn = 1.0f / (float)NSTEPS;
        #pragma unroll
        for (int i = tid; i < WEIGHT_FLOATS / 4; i += ROWS_PER_CTA) {
            sW4[i] = Wg[i];
            float4 v = Vg[i];
            v.x *= invn; v.y *= invn; v.z *= invn; v.w *= invn;
            sV4[i] = v;
        }
    }
    __syncthreads();

    const long long row = (long long)blockIdx.x * ROWS_PER_CTA + tid;

    // Load this thread's row: 16 floats -> 8 packed f32x2
    u64 h[8];
    {
        const float4* xr = reinterpret_cast<const float4*>(x + row * DD);
        #pragma unroll
        for (int q = 0; q < 4; q++) {
            float4 t = xr[q];
            h[2 * q]     = pack2(t.x, t.y);
            h[2 * q + 1] = pack2(t.z, t.w);
        }
    }

    const ulonglong2* sW = reinterpret_cast<const ulonglong2*>(smem);
    const ulonglong2* sV = reinterpret_cast<const ulonglong2*>(smem + WEIGHT_FLOATS);

    #pragma unroll 1
    for (int s = 0; s < NSTEPS; s++) {
        const ulonglong2* Ws = sW + s * (DD * DD / 4);   // 64 ulonglong2 per step
        const ulonglong2* Vs = sV + s * (DD * DD / 4);

        // ---- g = h @ W_s ----
        u64 acc[8];
        #pragma unroll
        for (int i = 0; i < 8; i++) acc[i] = 0ULL;       // (0.0f, 0.0f)

        #pragma unroll
        for (int kp = 0; kp < 8; kp++) {
            float a, b;
            unpack2(h[kp], a, b);                        // h[2kp], h[2kp+1]
            const u64 ha = pack2(a, a);
            const u64 hb = pack2(b, b);
            const int ka = (2 * kp) * 4;
            const int kb = (2 * kp + 1) * 4;
            #pragma unroll
            for (int q = 0; q < 4; q++) {
                ulonglong2 wa = Ws[ka + q];              // W[2kp][4q..4q+3] (broadcast LDS.128)
                acc[2 * q]     = fma2(ha, wa.x, acc[2 * q]);
                acc[2 * q + 1] = fma2(ha, wa.y, acc[2 * q + 1]);
            }
            #pragma unroll
            for (int q = 0; q < 4; q++) {
                ulonglong2 wb = Ws[kb + q];
                acc[2 * q]     = fma2(hb, wb.x, acc[2 * q]);
                acc[2 * q + 1] = fma2(hb, wb.y, acc[2 * q + 1]);
            }
        }

        // ---- g = GELU(g), exact erf variant ----
        #pragma unroll
        for (int i = 0; i < 8; i++) {
            float a, b;
            unpack2(acc[i], a, b);
            a = gelu_exact(a);
            b = gelu_exact(b);
            acc[i] = pack2(a, b);
        }

        // ---- h += g @ (V_s / 64)  (residual folded into accumulation) ----
        #pragma unroll
        for (int kp = 0; kp < 8; kp++) {
            float a, b;
            unpack2(acc[kp], a, b);
            const u64 ga = pack2(a, a);
            const u64 gb = pack2(b, b);
            const int ka = (2 * kp) * 4;
            const int kb = (2 * kp + 1) * 4;
            #pragma unroll
            for (int q = 0; q < 4; q++) {
                ulonglong2 va = Vs[ka + q];
                h[2 * q]     = fma2(ga, va.x, h[2 * q]);
                h[2 * q + 1] = fma2(ga, va.y, h[2 * q + 1]);
            }
            #pragma unroll
            for (int q = 0; q < 4; q++) {
                ulonglong2 vb = Vs[kb + q];
                h[2 * q]     = fma2(gb, vb.x, h[2 * q]);
                h[2 * q + 1] = fma2(gb, vb.y, h[2 * q + 1]);
            }
        }
    }

    // Store result row
    {
        float4* orow = reinterpret_cast<float4*>(out + row * DD);
        #pragma unroll
        for (int q = 0; q < 4; q++) {
            float4 t;
            unpack2(h[2 * q],     t.x, t.y);
            unpack2(h[2 * q + 1], t.z, t.w);
            orow[q] = t;
        }
    }
}

extern "C" void kernel_launch(void* const* d_in, const int* in_sizes, int n_in,
                              void* d_out, int out_size) {
    const float* x = (const float*)d_in[0];
    const float* W = (const float*)d_in[1];
    const float* V = (const float*)d_in[2];
    float* out = (float*)d_out;

    static bool attr_set = false;
    if (!attr_set) {
        cudaFuncSetAttribute(resnet_steps_kernel,
                             cudaFuncAttributeMaxDynamicSharedMemorySize, SMEM_BYTES);
        attr_set = true;
    }

    const long long batch = (long long)in_sizes[0] / DD;   // 2^21
    const int grid = (int)((batch + ROWS_PER_CTA - 1) / ROWS_PER_CTA);
    resnet_steps_kernel<<<grid, ROWS_PER_CTA, SMEM_BYTES>>>(x, W, V, out);
}

// round 2
// speedup vs baseline: 1.4815x; 1.4815x over previous
#include <cuda_runtime.h>
#include <cstdint>

#define NSTEPS 64
#define DD 16
#define THREADS 256
#define RPT 4
#define ROWS_PER_CTA (THREADS * RPT)
#define WEIGHT_FLOATS (NSTEPS * DD * DD)
#define SMEM_BYTES (2 * WEIGHT_FLOATS * 4)   // 128 KB: W then V/64

typedef unsigned long long u64;

// ---- packed f32x2 helpers (sm_103a) ----
__device__ __forceinline__ u64 pack2(float lo, float hi) {
    u64 r;
    asm("mov.b64 %0, {%1, %2};" : "=l"(r) : "f"(lo), "f"(hi));
    return r;
}
__device__ __forceinline__ void unpack2(u64 v, float& lo, float& hi) {
    asm("mov.b64 {%0, %1}, %2;" : "=f"(lo), "=f"(hi) : "l"(v));
}
__device__ __forceinline__ u64 fma2(u64 a, u64 b, u64 c) {
    u64 d;
    asm("fma.rn.f32x2 %0, %1, %2, %3;" : "=l"(d) : "l"(a), "l"(b), "l"(c));
    return d;
}

__device__ __forceinline__ float gelu_exact(float x) {
    return 0.5f * x * (1.0f + erff(x * 0.70710678118654752440f));
}

__global__ __launch_bounds__(THREADS)
void resnet_steps_kernel(const float* __restrict__ x,
                         const float* __restrict__ W,
                         const float* __restrict__ V,
                         float* __restrict__ out)
{
    extern __shared__ float smem[];   // [0,16384): W ; [16384,32768): V * (1/64)
    const int tid = threadIdx.x;

    // Cooperative weight load; V pre-scaled by 1/NSTEPS so the residual add
    // folds into the second matvec accumulation.
    {
        const float4* Wg = reinterpret_cast<const float4*>(W);
        const float4* Vg = reinterpret_cast<const float4*>(V);
        float4* sW4 = reinterpret_cast<float4*>(smem);
        float4* sV4 = reinterpret_cast<float4*>(smem + WEIGHT_FLOATS);
        const float invn = 1.0f / (float)NSTEPS;
        for (int i = tid; i < WEIGHT_FLOATS / 4; i += THREADS) {
            sW4[i] = Wg[i];
            float4 v = Vg[i];
            v.x *= invn; v.y *= invn; v.z *= invn; v.w *= invn;
            sV4[i] = v;
        }
    }
    __syncthreads();

    // Each thread owns RPT rows, strided by THREADS for coalesced gmem access.
    const long long base_row = (long long)blockIdx.x * ROWS_PER_CTA + tid;

    u64 h[RPT][8];
    #pragma unroll
    for (int r = 0; r < RPT; r++) {
        const float4* xr = reinterpret_cast<const float4*>(x + (base_row + (long long)r * THREADS) * DD);
        #pragma unroll
        for (int q = 0; q < 4; q++) {
            float4 t = xr[q];
            h[r][2 * q]     = pack2(t.x, t.y);
            h[r][2 * q + 1] = pack2(t.z, t.w);
        }
    }

    const ulonglong2* sW = reinterpret_cast<const ulonglong2*>(smem);
    const ulonglong2* sV = reinterpret_cast<const ulonglong2*>(smem + WEIGHT_FLOATS);

    #pragma unroll 1
    for (int s = 0; s < NSTEPS; s++) {
        const ulonglong2* Ws = sW + s * (DD * DD / 4);   // 64 ulonglong2 / step
        const ulonglong2* Vs = sV + s * (DD * DD / 4);

        // ---- g = h @ W_s ----
        u64 acc[RPT][8];
        #pragma unroll
        for (int r = 0; r < RPT; r++)
            #pragma unroll
            for (int i = 0; i < 8; i++) acc[r][i] = 0ULL;

        #pragma unroll 1
        for (int kp = 0; kp < 8; kp++) {
            // rows 2kp, 2kp+1 of W_s: 8 LDS.128, reused by all RPT rows
            ulonglong2 w0 = Ws[kp * 8 + 0];
            ulonglong2 w1 = Ws[kp * 8 + 1];
            ulonglong2 w2 = Ws[kp * 8 + 2];
            ulonglong2 w3 = Ws[kp * 8 + 3];
            ulonglong2 w4 = Ws[kp * 8 + 4];
            ulonglong2 w5 = Ws[kp * 8 + 5];
            ulonglong2 w6 = Ws[kp * 8 + 6];
            ulonglong2 w7 = Ws[kp * 8 + 7];
            #pragma unroll
            for (int r = 0; r < RPT; r++) {
                float a, b;
                unpack2(h[r][kp], a, b);
                const u64 ha = pack2(a, a);
                const u64 hb = pack2(b, b);
                acc[r][0] = fma2(ha, w0.x, acc[r][0]);
                acc[r][1] = fma2(ha, w0.y, acc[r][1]);
                acc[r][2] = fma2(ha, w1.x, acc[r][2]);
                acc[r][3] = fma2(ha, w1.y, acc[r][3]);
                acc[r][4] = fma2(ha, w2.x, acc[r][4]);
                acc[r][5] = fma2(ha, w2.y, acc[r][5]);
                acc[r][6] = fma2(ha, w3.x, acc[r][6]);
                acc[r][7] = fma2(ha, w3.y, acc[r][7]);
                acc[r][0] = fma2(hb, w4.x, acc[r][0]);
                acc[r][1] = fma2(hb, w4.y, acc[r][1]);
                acc[r][2] = fma2(hb, w5.x, acc[r][2]);
                acc[r][3] = fma2(hb, w5.y, acc[r][3]);
                acc[r][4] = fma2(hb, w6.x, acc[r][4]);
                acc[r][5] = fma2(hb, w6.y, acc[r][5]);
                acc[r][6] = fma2(hb, w7.x, acc[r][6]);
                acc[r][7] = fma2(hb, w7.y, acc[r][7]);
            }
        }

        // ---- h += GELU(g) @ (V_s/64), GELU fused into broadcast build ----
        #pragma unroll 1
        for (int kp = 0; kp < 8; kp++) {
            ulonglong2 v0 = Vs[kp * 8 + 0];
            ulonglong2 v1 = Vs[kp * 8 + 1];
            ulonglong2 v2 = Vs[kp * 8 + 2];
            ulonglong2 v3 = Vs[kp * 8 + 3];
            ulonglong2 v4 = Vs[kp * 8 + 4];
            ulonglong2 v5 = Vs[kp * 8 + 5];
            ulonglong2 v6 = Vs[kp * 8 + 6];
            ulonglong2 v7 = Vs[kp * 8 + 7];
            #pragma unroll
            for (int r = 0; r < RPT; r++) {
                float a, b;
                unpack2(acc[r][kp], a, b);
                a = gelu_exact(a);
                b = gelu_exact(b);
                const u64 ga = pack2(a, a);
                const u64 gb = pack2(b, b);
                h[r][0] = fma2(ga, v0.x, h[r][0]);
                h[r][1] = fma2(ga, v0.y, h[r][1]);
                h[r][2] = fma2(ga, v1.x, h[r][2]);
                h[r][3] = fma2(ga, v1.y, h[r][3]);
                h[r][4] = fma2(ga, v2.x, h[r][4]);
                h[r][5] = fma2(ga, v2.y, h[r][5]);
                h[r][6] = fma2(ga, v3.x, h[r][6]);
                h[r][7] = fma2(ga, v3.y, h[r][7]);
                h[r][0] = fma2(gb, v4.x, h[r][0]);
                h[r][1] = fma2(gb, v4.y, h[r][1]);
                h[r][2] = fma2(gb, v5.x, h[r][2]);
                h[r][3] = fma2(gb, v5.y, h[r][3]);
                h[r][4] = fma2(gb, v6.x, h[r][4]);
                h[r][5] = fma2(gb, v6.y, h[r][5]);
                h[r][6] = fma2(gb, v7.x, h[r][6]);
                h[r][7] = fma2(gb, v7.y, h[r][7]);
            }
        }
    }

    // Store result rows
    #pragma unroll
    for (int r = 0; r < RPT; r++) {
        float4* orow = reinterpret_cast<float4*>(out + (base_row + (long long)r * THREADS) * DD);
        #pragma unroll
        for (int q = 0; q < 4; q++) {
            float4 t;
            unpack2(h[r][2 * q],     t.x, t.y);
            unpack2(h[r][2 * q + 1], t.z, t.w);
            orow[q] = t;
        }
    }
}

extern "C" void kernel_launch(void* const* d_in, const int* in_sizes, int n_in,
                              void* d_out, int out_size) {
    const float* x = (const float*)d_in[0];
    const float* W = (const float*)d_in[1];
    const float* V = (const float*)d_in[2];
    float* out = (float*)d_out;

    static bool attr_set = false;
    if (!attr_set) {
        cudaFuncSetAttribute(resnet_steps_kernel,
                             cudaFuncAttributeMaxDynamicSharedMemorySize, SMEM_BYTES);
        attr_set = true;
    }

    const long long batch = (long long)in_sizes[0] / DD;   // 2^21
    const int grid = (int)((batch + ROWS_PER_CTA - 1) / ROWS_PER_CTA);
    resnet_steps_kernel<<<grid, THREADS, SMEM_BYTES>>>(x, W, V, out);
}

// round 3
// speedup vs baseline: 1.7168x; 1.1588x over previous
#include <cuda_runtime.h>
#include <cstdint>

#define NSTEPS 64
#define DD 16
#define THREADS 256
#define RPT 4
#define ROWS_PER_CTA (THREADS * RPT)
#define WEIGHT_FLOATS (NSTEPS * DD * DD)
#define SMEM_BYTES (2 * WEIGHT_FLOATS * 4)   // 128 KB: W then V/64

typedef unsigned long long u64;

// ---- packed f32x2 helpers (sm_103a) ----
__device__ __forceinline__ u64 pack2(float lo, float hi) {
    u64 r;
    asm("mov.b64 %0, {%1, %2};" : "=l"(r) : "f"(lo), "f"(hi));
    return r;
}
__device__ __forceinline__ void unpack2(u64 v, float& lo, float& hi) {
    asm("mov.b64 {%0, %1}, %2;" : "=f"(lo), "=f"(hi) : "l"(v));
}
__device__ __forceinline__ u64 fma2(u64 a, u64 b, u64 c) {
    u64 d;
    asm("fma.rn.f32x2 %0, %1, %2, %3;" : "=l"(d) : "l"(a), "l"(b), "l"(c));
    return d;
}
__device__ __forceinline__ u64 mul2(u64 a, u64 b) {
    u64 d;
    asm("mul.rn.f32x2 %0, %1, %2;" : "=l"(d) : "l"(a), "l"(b));
    return d;
}
__device__ __forceinline__ float rcp_fast(float x) {
    float r;
    asm("rcp.approx.ftz.f32 %0, %1;" : "=f"(r) : "f"(x));
    return r;
}
__device__ __forceinline__ float ex2_fast(float x) {
    float r;
    asm("ex2.approx.ftz.f32 %0, %1;" : "=f"(r) : "f"(x));
    return r;
}

// A&S 7.1.26 erf constants
#define ERF_P   0.3275911f
#define ERF_A1  0.254829592f
#define ERF_A2 -0.284496736f
#define ERF_A3  1.421413741f
#define ERF_A4 -1.453152027f
#define ERF_A5  1.061405429f
#define INV_SQRT2 0.70710678118654752440f
#define NEG_LOG2E -1.44269504088896340736f

struct GeluConsts {
    u64 c5n, c4n, c3n, c2n, c1n;  // negated A&S coefs, duplicated
    u64 one2, half2;
};

// gelu on a packed pair: returns (gelu(x), gelu(y))
__device__ __forceinline__ u64 gelu2(u64 xy, const GeluConsts& gc) {
    float x, y;
    unpack2(xy, x, y);
    float ax = fabsf(x) * INV_SQRT2;
    float ay = fabsf(y) * INV_SQRT2;
    float tx = rcp_fast(fmaf(ERF_P, ax, 1.0f));
    float ty = rcp_fast(fmaf(ERF_P, ay, 1.0f));
    float ex = ex2_fast(ax * ax * NEG_LOG2E);
    float ey = ex2_fast(ay * ay * NEG_LOG2E);
    u64 t2 = pack2(tx, ty);
    u64 e2 = pack2(ex, ey);
    // Pn = -(a5 t^5 + ... + a1 t) via negated coefs
    u64 p = fma2(gc.c5n, t2, gc.c4n);
    p = fma2(p, t2, gc.c3n);
    p = fma2(p, t2, gc.c2n);
    p = fma2(p, t2, gc.c1n);
    p = mul2(p, t2);
    u64 E2 = fma2(p, e2, gc.one2);          // E = 1 - P(t)*e^{-z^2}  (per lane)
    u64 habs = mul2(xy & 0x7fffffff7fffffffULL, gc.half2);   // 0.5*|x|
    u64 hx = mul2(xy, gc.half2);                             // 0.5*x
    return fma2(habs, E2, hx);              // 0.5x + 0.5|x|*E
}

__global__ __launch_bounds__(THREADS)
void resnet_steps_kernel(const float* __restrict__ x,
                         const float* __restrict__ W,
                         const float* __restrict__ V,
                         float* __restrict__ out)
{
    extern __shared__ float smem[];   // [0,16384): W ; [16384,32768): V * (1/64)
    const int tid = threadIdx.x;

    {
        const float4* Wg = reinterpret_cast<const float4*>(W);
        const float4* Vg = reinterpret_cast<const float4*>(V);
        float4* sW4 = reinterpret_cast<float4*>(smem);
        float4* sV4 = reinterpret_cast<float4*>(smem + WEIGHT_FLOATS);
        const float invn = 1.0f / (float)NSTEPS;
        for (int i = tid; i < WEIGHT_FLOATS / 4; i += THREADS) {
            sW4[i] = Wg[i];
            float4 v = Vg[i];
            v.x *= invn; v.y *= invn; v.z *= invn; v.w *= invn;
            sV4[i] = v;
        }
    }
    __syncthreads();

    GeluConsts gc;
    gc.c5n = pack2(-ERF_A5, -ERF_A5);
    gc.c4n = pack2(-ERF_A4, -ERF_A4);
    gc.c3n = pack2(-ERF_A3, -ERF_A3);
    gc.c2n = pack2(-ERF_A2, -ERF_A2);
    gc.c1n = pack2(-ERF_A1, -ERF_A1);
    gc.one2 = pack2(1.0f, 1.0f);
    gc.half2 = pack2(0.5f, 0.5f);

    const long long base_row = (long long)blockIdx.x * ROWS_PER_CTA + tid;

    u64 h[RPT][8];
    #pragma unroll
    for (int r = 0; r < RPT; r++) {
        const float4* xr = reinterpret_cast<const float4*>(x + (base_row + (long long)r * THREADS) * DD);
        #pragma unroll
        for (int q = 0; q < 4; q++) {
            float4 t = xr[q];
            h[r][2 * q]     = pack2(t.x, t.y);
            h[r][2 * q + 1] = pack2(t.z, t.w);
        }
    }

    const ulonglong2* sW = reinterpret_cast<const ulonglong2*>(smem);
    const ulonglong2* sV = reinterpret_cast<const ulonglong2*>(smem + WEIGHT_FLOATS);

    #pragma unroll 1
    for (int s = 0; s < NSTEPS; s++) {
        const ulonglong2* Ws = sW + s * (DD * DD / 4);
        const ulonglong2* Vs = sV + s * (DD * DD / 4);

        // ---- g = h @ W_s ----
        u64 acc[RPT][8];
        #pragma unroll
        for (int r = 0; r < RPT; r++)
            #pragma unroll
            for (int i = 0; i < 8; i++) acc[r][i] = 0ULL;

        #pragma unroll 1
        for (int kp = 0; kp < 8; kp++) {
            ulonglong2 w0 = Ws[kp * 8 + 0];
            ulonglong2 w1 = Ws[kp * 8 + 1];
            ulonglong2 w2 = Ws[kp * 8 + 2];
            ulonglong2 w3 = Ws[kp * 8 + 3];
            ulonglong2 w4 = Ws[kp * 8 + 4];
            ulonglong2 w5 = Ws[kp * 8 + 5];
            ulonglong2 w6 = Ws[kp * 8 + 6];
            ulonglong2 w7 = Ws[kp * 8 + 7];
            #pragma unroll
            for (int r = 0; r < RPT; r++) {
                float a, b;
                unpack2(h[r][kp], a, b);
                const u64 ha = pack2(a, a);
                const u64 hb = pack2(b, b);
                acc[r][0] = fma2(ha, w0.x, acc[r][0]);
                acc[r][1] = fma2(ha, w0.y, acc[r][1]);
                acc[r][2] = fma2(ha, w1.x, acc[r][2]);
                acc[r][3] = fma2(ha, w1.y, acc[r][3]);
                acc[r][4] = fma2(ha, w2.x, acc[r][4]);
                acc[r][5] = fma2(ha, w2.y, acc[r][5]);
                acc[r][6] = fma2(ha, w3.x, acc[r][6]);
                acc[r][7] = fma2(ha, w3.y, acc[r][7]);
                acc[r][0] = fma2(hb, w4.x, acc[r][0]);
                acc[r][1] = fma2(hb, w4.y, acc[r][1]);
                acc[r][2] = fma2(hb, w5.x, acc[r][2]);
                acc[r][3] = fma2(hb, w5.y, acc[r][3]);
                acc[r][4] = fma2(hb, w6.x, acc[r][4]);
                acc[r][5] = fma2(hb, w6.y, acc[r][5]);
                acc[r][6] = fma2(hb, w7.x, acc[r][6]);
                acc[r][7] = fma2(hb, w7.y, acc[r][7]);
            }
        }

        // ---- h += GELU(g) @ (V_s/64); fast packed A&S erf ----
        #pragma unroll 1
        for (int kp = 0; kp < 8; kp++) {
            ulonglong2 v0 = Vs[kp * 8 + 0];
            ulonglong2 v1 = Vs[kp * 8 + 1];
            ulonglong2 v2 = Vs[kp * 8 + 2];
            ulonglong2 v3 = Vs[kp * 8 + 3];
            ulonglong2 v4 = Vs[kp * 8 + 4];
            ulonglong2 v5 = Vs[kp * 8 + 5];
            ulonglong2 v6 = Vs[kp * 8 + 6];
            ulonglong2 v7 = Vs[kp * 8 + 7];
            #pragma unroll
            for (int r = 0; r < RPT; r++) {
                u64 g2 = gelu2(acc[r][kp], gc);
                float a, b;
                unpack2(g2, a, b);
                const u64 ga = pack2(a, a);
                const u64 gb = pack2(b, b);
                h[r][0] = fma2(ga, v0.x, h[r][0]);
                h[r][1] = fma2(ga, v0.y, h[r][1]);
                h[r][2] = fma2(ga, v1.x, h[r][2]);
                h[r][3] = fma2(ga, v1.y, h[r][3]);
                h[r][4] = fma2(ga, v2.x, h[r][4]);
                h[r][5] = fma2(ga, v2.y, h[r][5]);
                h[r][6] = fma2(ga, v3.x, h[r][6]);
                h[r][7] = fma2(ga, v3.y, h[r][7]);
                h[r][0] = fma2(gb, v4.x, h[r][0]);
                h[r][1] = fma2(gb, v4.y, h[r][1]);
                h[r][2] = fma2(gb, v5.x, h[r][2]);
                h[r][3] = fma2(gb, v5.y, h[r][3]);
                h[r][4] = fma2(gb, v6.x, h[r][4]);
                h[r][5] = fma2(gb, v6.y, h[r][5]);
                h[r][6] = fma2(gb, v7.x, h[r][6]);
                h[r][7] = fma2(gb, v7.y, h[r][7]);
            }
        }
    }

    #pragma unroll
    for (int r = 0; r < RPT; r++) {
        float4* orow = reinterpret_cast<float4*>(out + (base_row + (long long)r * THREADS) * DD);
        #pragma unroll
        for (int q = 0; q < 4; q++) {
            float4 t;
            unpack2(h[r][2 * q],     t.x, t.y);
            unpack2(h[r][2 * q + 1], t.z, t.w);
            orow[q] = t;
        }
    }
}

extern "C" void kernel_launch(void* const* d_in, const int* in_sizes, int n_in,
                              void* d_out, int out_size) {
    const float* x = (const float*)d_in[0];
    const float* W = (const float*)d_in[1];
    const float* V = (const float*)d_in[2];
    float* out = (float*)d_out;

    static bool attr_set = false;
    if (!attr_set) {
        cudaFuncSetAttribute(resnet_steps_kernel,
                             cudaFuncAttributeMaxDynamicSharedMemorySize, SMEM_BYTES);
        attr_set = true;
    }

    const long long batch = (long long)in_sizes[0] / DD;   // 2^21
    const int grid = (int)((batch + ROWS_PER_CTA - 1) / ROWS_PER_CTA);
    resnet_steps_kernel<<<grid, THREADS, SMEM_BYTES>>>(x, W, V, out);
}

// round 4
// speedup vs baseline: 2.0694x; 1.2054x over previous
#include <cuda_runtime.h>
#include <cstdint>

#define NSTEPS 64
#define DD 16
#define THREADS 512
#define RPT 2
#define ROWS_PER_CTA (THREADS * RPT)
#define WEIGHT_FLOATS (NSTEPS * DD * DD)
#define SMEM_BYTES (2 * WEIGHT_FLOATS * 4)   // 128 KB: W then V/64

typedef unsigned long long u64;

// ---- packed f32x2 helpers (sm_103a) ----
__device__ __forceinline__ u64 pack2(float lo, float hi) {
    u64 r;
    asm("mov.b64 %0, {%1, %2};" : "=l"(r) : "f"(lo), "f"(hi));
    return r;
}
__device__ __forceinline__ void unpack2(u64 v, float& lo, float& hi) {
    asm("mov.b64 {%0, %1}, %2;" : "=f"(lo), "=f"(hi) : "l"(v));
}
__device__ __forceinline__ u64 fma2(u64 a, u64 b, u64 c) {
    u64 d;
    asm("fma.rn.f32x2 %0, %1, %2, %3;" : "=l"(d) : "l"(a), "l"(b), "l"(c));
    return d;
}
__device__ __forceinline__ u64 mul2(u64 a, u64 b) {
    u64 d;
    asm("mul.rn.f32x2 %0, %1, %2;" : "=l"(d) : "l"(a), "l"(b));
    return d;
}
__device__ __forceinline__ float rcp_fast(float x) {
    float r;
    asm("rcp.approx.ftz.f32 %0, %1;" : "=f"(r) : "f"(x));
    return r;
}
__device__ __forceinline__ float ex2_fast(float x) {
    float r;
    asm("ex2.approx.ftz.f32 %0, %1;" : "=f"(r) : "f"(x));
    return r;
}

// A&S 7.1.26 erf constants
#define ERF_P   0.3275911f
#define ERF_A1  0.254829592f
#define ERF_A2 -0.284496736f
#define ERF_A3  1.421413741f
#define ERF_A4 -1.453152027f
#define ERF_A5  1.061405429f
#define INV_SQRT2 0.70710678118654752440f
#define NEG_LOG2E -1.44269504088896340736f

// gelu on a packed pair: returns (gelu(x), gelu(y)); erf via A&S 7.1.26
__device__ __forceinline__ u64 gelu2(u64 xy) {
    float x, y;
    unpack2(xy, x, y);
    float ax = fabsf(x) * INV_SQRT2;
    float ay = fabsf(y) * INV_SQRT2;
    float tx = rcp_fast(fmaf(ERF_P, ax, 1.0f));
    float ty = rcp_fast(fmaf(ERF_P, ay, 1.0f));
    float ex = ex2_fast(ax * ax * NEG_LOG2E);
    float ey = ex2_fast(ay * ay * NEG_LOG2E);
    u64 t2 = pack2(tx, ty);
    u64 e2 = pack2(ex, ey);
    // P = -(a5 t^5 + ... + a1 t) via negated coefs (packed Horner)
    u64 p = fma2(pack2(-ERF_A5, -ERF_A5), t2, pack2(-ERF_A4, -ERF_A4));
    p = fma2(p, t2, pack2(-ERF_A3, -ERF_A3));
    p = fma2(p, t2, pack2(-ERF_A2, -ERF_A2));
    p = fma2(p, t2, pack2(-ERF_A1, -ERF_A1));
    p = mul2(p, t2);
    u64 E2 = fma2(p, e2, pack2(1.0f, 1.0f));               // E = 1 - P(t)*e^{-z^2}
    u64 half2 = pack2(0.5f, 0.5f);
    u64 habs = mul2(xy & 0x7fffffff7fffffffULL, half2);     // 0.5*|x|
    u64 hx = mul2(xy, half2);                               // 0.5*x
    return fma2(habs, E2, hx);                              // 0.5x + 0.5|x|*E
}

__global__ __launch_bounds__(THREADS)
void resnet_steps_kernel(const float* __restrict__ x,
                         const float* __restrict__ W,
                         const float* __restrict__ V,
                         float* __restrict__ out)
{
    extern __shared__ float smem[];   // [0,16384): W ; [16384,32768): V * (1/64)
    const int tid = threadIdx.x;

    {
        const float4* Wg = reinterpret_cast<const float4*>(W);
        const float4* Vg = reinterpret_cast<const float4*>(V);
        float4* sW4 = reinterpret_cast<float4*>(smem);
        float4* sV4 = reinterpret_cast<float4*>(smem + WEIGHT_FLOATS);
        const float invn = 1.0f / (float)NSTEPS;
        for (int i = tid; i < WEIGHT_FLOATS / 4; i += THREADS) {
            sW4[i] = Wg[i];
            float4 v = Vg[i];
            v.x *= invn; v.y *= invn; v.z *= invn; v.w *= invn;
            sV4[i] = v;
        }
    }
    __syncthreads();

    const long long base_row = (long long)blockIdx.x * ROWS_PER_CTA + tid;

    u64 h[RPT][8];
    #pragma unroll
    for (int r = 0; r < RPT; r++) {
        const float4* xr = reinterpret_cast<const float4*>(x + (base_row + (long long)r * THREADS) * DD);
        #pragma unroll
        for (int q = 0; q < 4; q++) {
            float4 t = xr[q];
            h[r][2 * q]     = pack2(t.x, t.y);
            h[r][2 * q + 1] = pack2(t.z, t.w);
        }
    }

    const ulonglong2* sW = reinterpret_cast<const ulonglong2*>(smem);
    const ulonglong2* sV = reinterpret_cast<const ulonglong2*>(smem + WEIGHT_FLOATS);

    #pragma unroll 1
    for (int s = 0; s < NSTEPS; s++) {
        const ulonglong2* Ws = sW + s * (DD * DD / 4);
        const ulonglong2* Vs = sV + s * (DD * DD / 4);

        // ---- g = h @ W_s ----
        u64 acc[RPT][8];
        #pragma unroll
        for (int r = 0; r < RPT; r++)
            #pragma unroll
            for (int i = 0; i < 8; i++) acc[r][i] = 0ULL;

        #pragma unroll 1
        for (int kp = 0; kp < 8; kp++) {
            ulonglong2 w0 = Ws[kp * 8 + 0];
            ulonglong2 w1 = Ws[kp * 8 + 1];
            ulonglong2 w2 = Ws[kp * 8 + 2];
            ulonglong2 w3 = Ws[kp * 8 + 3];
            ulonglong2 w4 = Ws[kp * 8 + 4];
            ulonglong2 w5 = Ws[kp * 8 + 5];
            ulonglong2 w6 = Ws[kp * 8 + 6];
            ulonglong2 w7 = Ws[kp * 8 + 7];
            #pragma unroll
            for (int r = 0; r < RPT; r++) {
                float a, b;
                unpack2(h[r][kp], a, b);
                const u64 ha = pack2(a, a);
                const u64 hb = pack2(b, b);
                acc[r][0] = fma2(ha, w0.x, acc[r][0]);
                acc[r][1] = fma2(ha, w0.y, acc[r][1]);
                acc[r][2] = fma2(ha, w1.x, acc[r][2]);
                acc[r][3] = fma2(ha, w1.y, acc[r][3]);
                acc[r][4] = fma2(ha, w2.x, acc[r][4]);
                acc[r][5] = fma2(ha, w2.y, acc[r][5]);
                acc[r][6] = fma2(ha, w3.x, acc[r][6]);
                acc[r][7] = fma2(ha, w3.y, acc[r][7]);
                acc[r][0] = fma2(hb, w4.x, acc[r][0]);
                acc[r][1] = fma2(hb, w4.y, acc[r][1]);
                acc[r][2] = fma2(hb, w5.x, acc[r][2]);
                acc[r][3] = fma2(hb, w5.y, acc[r][3]);
                acc[r][4] = fma2(hb, w6.x, acc[r][4]);
                acc[r][5] = fma2(hb, w6.y, acc[r][5]);
                acc[r][6] = fma2(hb, w7.x, acc[r][6]);
                acc[r][7] = fma2(hb, w7.y, acc[r][7]);
            }
        }

        // ---- h += GELU(g) @ (V_s/64); fast packed A&S erf ----
        #pragma unroll 1
        for (int kp = 0; kp < 8; kp++) {
            ulonglong2 v0 = Vs[kp * 8 + 0];
            ulonglong2 v1 = Vs[kp * 8 + 1];
            ulonglong2 v2 = Vs[kp * 8 + 2];
            ulonglong2 v3 = Vs[kp * 8 + 3];
            ulonglong2 v4 = Vs[kp * 8 + 4];
            ulonglong2 v5 = Vs[kp * 8 + 5];
            ulonglong2 v6 = Vs[kp * 8 + 6];
            ulonglong2 v7 = Vs[kp * 8 + 7];
            #pragma unroll
            for (int r = 0; r < RPT; r++) {
                u64 g2 = gelu2(acc[r][kp]);
                float a, b;
                unpack2(g2, a, b);
                const u64 ga = pack2(a, a);
                const u64 gb = pack2(b, b);
                h[r][0] = fma2(ga, v0.x, h[r][0]);
                h[r][1] = fma2(ga, v0.y, h[r][1]);
                h[r][2] = fma2(ga, v1.x, h[r][2]);
                h[r][3] = fma2(ga, v1.y, h[r][3]);
                h[r][4] = fma2(ga, v2.x, h[r][4]);
                h[r][5] = fma2(ga, v2.y, h[r][5]);
                h[r][6] = fma2(ga, v3.x, h[r][6]);
                h[r][7] = fma2(ga, v3.y, h[r][7]);
                h[r][0] = fma2(gb, v4.x, h[r][0]);
                h[r][1] = fma2(gb, v4.y, h[r][1]);
                h[r][2] = fma2(gb, v5.x, h[r][2]);
                h[r][3] = fma2(gb, v5.y, h[r][3]);
                h[r][4] = fma2(gb, v6.x, h[r][4]);
                h[r][5] = fma2(gb, v6.y, h[r][5]);
                h[r][6] = fma2(gb, v7.x, h[r][6]);
                h[r][7] = fma2(gb, v7.y, h[r][7]);
            }
        }
    }

    #pragma unroll
    for (int r = 0; r < RPT; r++) {
        float4* orow = reinterpret_cast<float4*>(out + (base_row + (long long)r * THREADS) * DD);
        #pragma unroll
        for (int q = 0; q < 4; q++) {
            float4 t;
            unpack2(h[r][2 * q],     t.x, t.y);
            unpack2(h[r][2 * q + 1], t.z, t.w);
            orow[q] = t;
        }
    }
}

extern "C" void kernel_launch(void* const* d_in, const int* in_sizes, int n_in,
                              void* d_out, int out_size) {
    const float* x = (const float*)d_in[0];
    const float* W = (const float*)d_in[1];
    const float* V = (const float*)d_in[2];
    float* out = (float*)d_out;

    static bool attr_set = false;
    if (!attr_set) {
        cudaFuncSetAttribute(resnet_steps_kernel,
                             cudaFuncAttributeMaxDynamicSharedMemorySize, SMEM_BYTES);
        attr_set = true;
    }

    const long long batch = (long long)in_sizes[0] / DD;   // 2^21
    const int grid = (int)((batch + ROWS_PER_CTA - 1) / ROWS_PER_CTA);
    resnet_steps_kernel<<<grid, THREADS, SMEM_BYTES>>>(x, W, V, out);
}